// round 6
// baseline (speedup 1.0000x reference)
#include <cuda_runtime.h>
#include <stdint.h>
#include <math.h>

#define Bb 64
#define Tt 256
#define Dd 409
#define Hh 1024
#define G4 4096
#define TB 16384   // B*T

typedef unsigned long long u64;

// All row indices are m = b*Tt + t  (native [B,T,...] order; NO remapping anywhere)
__device__ float g_gx_enc[(size_t)TB*G4];   // x[m] @ Wih^T + b
__device__ float g_gx_dec[(size_t)TB*G4];   // x[m-1 or 0] @ Wih^T + b
__device__ float g_hs[(size_t)TB*Hh];       // decoder h, row m = b*Tt+t
__device__ float g_h0[Bb*Hh];
__device__ float g_h1[Bb*Hh];
__device__ float g_c[Bb*Hh];

__device__ __forceinline__ void fma2(u64& d, u64 a, u64 b){
    asm("fma.rn.f32x2 %0, %1, %2, %0;" : "+l"(d) : "l"(a), "l"(b));
}
__device__ __forceinline__ float hsum(u64 v){
    float x, y;
    asm("mov.b64 {%0,%1}, %2;" : "=f"(x), "=f"(y) : "l"(v));
    return x + y;
}

__global__ void k_zero2(float* a, float* b, int n){
    int i = blockIdx.x*blockDim.x + threadIdx.x;
    if (i < n){ a[i] = 0.f; b[i] = 0.f; }
}

__global__ void k_copy(const float* __restrict__ src, float* __restrict__ dst, int n){
    int i = blockIdx.x*blockDim.x + threadIdx.x;
    if (i < n) dst[i] = src[i];
}

// ---- gates from x: gx[m][n] = x_row(m) . Wih[n] + bias[n]
// x native [B,T,D] row-major; row m reads x + m*409 (shifted: m-1, zero if t==0).
// BM=128, BN=64, K chunk 16 (scalar stage handles odd D=409; f32x2 compute).
__global__ void k_gates(const float* __restrict__ x, const float* __restrict__ W,
                        const float* __restrict__ bias, float* __restrict__ gx,
                        int shifted){
    __shared__ float Asf[8*260];   // pairs: u64 view stride 130
    __shared__ float Bsf[8*132];   // u64 view stride 66

    int tid = threadIdx.x, tm = tid >> 4, tn = tid & 15;
    int m0 = blockIdx.y * 128, n0 = blockIdx.x * 64;

    u64 acc[8][4];
    #pragma unroll
    for (int i=0;i<8;i++)
        #pragma unroll
        for (int j=0;j<4;j++) acc[i][j] = 0ull;

    for (int kt = 0; kt < 26; kt++){
        int k0 = kt * 16;
        #pragma unroll
        for (int q = 0; q < 8; q++){                 // 2048 = 128 rows x 16 k
            int idx = tid + q*256, ml = idx >> 4, kk = idx & 15;
            int k = k0 + kk, m = m0 + ml;
            float v = 0.f;
            if (k < Dd){
                if (!shifted)            v = x[(size_t)m*Dd + k];
                else if ((m & 255) != 0) v = x[(size_t)(m-1)*Dd + k];
            }
            Asf[(kk>>1)*260 + 2*ml + (kk&1)] = v;
        }
        #pragma unroll
        for (int q = 0; q < 4; q++){                 // 1024 = 64 rows x 16 k
            int idx = tid + q*256, nl = idx >> 4, kk = idx & 15;
            int k = k0 + kk;
            float v = (k < Dd) ? W[(size_t)(n0 + nl)*Dd + k] : 0.f;
            Bsf[(kk>>1)*132 + 2*nl + (kk&1)] = v;
        }
        __syncthreads();
        const u64* Au = (const u64*)Asf;
        const u64* Bu = (const u64*)Bsf;
        #pragma unroll
        for (int kp = 0; kp < 8; kp++){
            u64 a[8], b[4];
            #pragma unroll
            for (int i=0;i<8;i++) a[i] = Au[kp*130 + i*16 + tm];
            #pragma unroll
            for (int j=0;j<4;j++) b[j] = Bu[kp*66 + j*16 + tn];
            #pragma unroll
            for (int i=0;i<8;i++)
                #pragma unroll
                for (int j=0;j<4;j++) fma2(acc[i][j], a[i], b[j]);
        }
        __syncthreads();
    }
    #pragma unroll
    for (int j=0;j<4;j++){
        int n = n0 + j*16 + tn;
        float bv = bias[n];
        #pragma unroll
        for (int i=0;i<8;i++)
            gx[(size_t)(m0 + i*16 + tm)*G4 + n] = hsum(acc[i][j]) + bv;
    }
}

// ---- recurrent step: G = h @ Whh^T + fused pointwise. 128 CTAs x 256 thr.
// Explicit hin/hout pointers (parity handled on host). gx rows m = b*Tt + t.
__global__ void k_step(const float* __restrict__ Whh, const float* __restrict__ gx,
                       const float* __restrict__ hin_, float* __restrict__ hout,
                       float* __restrict__ hs, int t){
    const float2* __restrict__ W2 = (const float2*)Whh;
    const float2* __restrict__ H2 = (const float2*)hin_;

    __shared__ float2 As2[16*67];
    __shared__ float2 Bs2[16*35];

    int tid = threadIdx.x, tm = tid >> 3, tn = tid & 7;
    int base = blockIdx.x * 8;

    u64 acc[2][4];
    #pragma unroll
    for (int i=0;i<2;i++)
        #pragma unroll
        for (int j=0;j<4;j++) acc[i][j] = 0ull;

    for (int kt = 0; kt < 32; kt++){
        int kb = kt * 16;
        #pragma unroll
        for (int q = 0; q < 4; q++){                 // 1024 = 64 rows x 16 kp
            int idx = tid + q*256, ml = idx >> 4, kp = idx & 15;
            As2[kp*67 + ml] = H2[(size_t)ml*512 + kb + kp];
        }
        #pragma unroll
        for (int q = 0; q < 2; q++){                 // 512 = 32 rows x 16 kp
            int idx = tid + q*256, nl = idx >> 4, kp = idx & 15;
            int wrow = ((nl >> 3) << 10) + base + (nl & 7);   // gate*1024 + col
            Bs2[kp*35 + nl] = W2[(size_t)wrow*512 + kb + kp];
        }
        __syncthreads();
        #pragma unroll
        for (int kp = 0; kp < 16; kp++){
            u64 a0 = *(const u64*)&As2[kp*67 + tm];
            u64 a1 = *(const u64*)&As2[kp*67 + 32 + tm];
            u64 b[4];
            #pragma unroll
            for (int j=0;j<4;j++) b[j] = *(const u64*)&Bs2[kp*35 + j*8 + tn];
            #pragma unroll
            for (int j=0;j<4;j++){ fma2(acc[0][j], a0, b[j]); fma2(acc[1][j], a1, b[j]); }
        }
        __syncthreads();
    }

    int gc = base + tn;
    #pragma unroll
    for (int i = 0; i < 2; i++){
        int m = i*32 + tm;                           // batch index
        const float* gxr = gx + ((size_t)m*Tt + t)*G4;
        float iv = hsum(acc[i][0]) + gxr[          gc];
        float fv = hsum(acc[i][1]) + gxr[  Hh   + gc];
        float gv = hsum(acc[i][2]) + gxr[2*Hh   + gc];
        float ov = hsum(acc[i][3]) + gxr[3*Hh   + gc];
        float si = 1.f / (1.f + expf(-iv));
        float sf = 1.f / (1.f + expf(-fv));
        float so = 1.f / (1.f + expf(-ov));
        float c  = sf * g_c[m*Hh + gc] + si * tanhf(gv);
        float h  = so * tanhf(c);
        g_c[m*Hh + gc]  = c;
        hout[m*Hh + gc] = h;
        if (hs) hs[((size_t)m*Tt + t)*Hh + gc] = h;
    }
}

// ---- head: seq[m][n] = hs[m] . pred_W[n] + pred_b[n]; rows m = b*Tt+t identity.
__global__ void k_head(const float* __restrict__ P, const float* __restrict__ pb,
                       float* __restrict__ seq){
    const float2* __restrict__ H2 = (const float2*)g_hs;
    const float2* __restrict__ P2 = (const float2*)P;

    __shared__ float2 As2[8*130];
    __shared__ float2 Bs2[8*66];

    int tid = threadIdx.x, tm = tid >> 4, tn = tid & 15;
    int m0 = blockIdx.y * 128, n0 = blockIdx.x * 64;

    u64 acc[8][4];
    #pragma unroll
    for (int i=0;i<8;i++)
        #pragma unroll
        for (int j=0;j<4;j++) acc[i][j] = 0ull;

    for (int kt = 0; kt < 64; kt++){
        int kb = kt * 8;
        #pragma unroll
        for (int q = 0; q < 4; q++){
            int idx = tid + q*256, ml = idx >> 3, kp = idx & 7;
            As2[kp*130 + ml] = H2[(size_t)(m0 + ml)*512 + kb + kp];
        }
        #pragma unroll
        for (int q = 0; q < 2; q++){
            int idx = tid + q*256, nl = idx >> 3, kp = idx & 7;
            int row = n0 + nl;
            float2 v = make_float2(0.f, 0.f);
            if (row < Dd) v = P2[(size_t)row*512 + kb + kp];
            Bs2[kp*66 + nl] = v;
        }
        __syncthreads();
        #pragma unroll
        for (int kp = 0; kp < 8; kp++){
            u64 a[8], b[4];
            #pragma unroll
            for (int i=0;i<8;i++) a[i] = *(const u64*)&As2[kp*130 + i*16 + tm];
            #pragma unroll
            for (int j=0;j<4;j++) b[j] = *(const u64*)&Bs2[kp*66 + j*16 + tn];
            #pragma unroll
            for (int i=0;i<8;i++)
                #pragma unroll
                for (int j=0;j<4;j++) fma2(acc[i][j], a[i], b[j]);
        }
        __syncthreads();
    }
    #pragma unroll
    for (int j=0;j<4;j++){
        int n = n0 + j*16 + tn;
        if (n >= Dd) continue;
        float bv = pb[n];
        #pragma unroll
        for (int i=0;i<8;i++)
            seq[(size_t)(m0 + i*16 + tm)*Dd + n] = hsum(acc[i][j]) + bv;
    }
}

static float* symaddr(const void* sym){
    void* p = 0;
    cudaGetSymbolAddress(&p, sym);
    return (float*)p;
}

extern "C" void kernel_launch(void* const* d_in, const int* in_sizes, int n_in,
                              void* d_out, int out_size) {
    const float* inputs  = (const float*)d_in[0];
    const float* enc_Wih = (const float*)d_in[1];
    const float* enc_Whh = (const float*)d_in[2];
    const float* enc_b   = (const float*)d_in[3];
    const float* dec_Wih = (const float*)d_in[4];
    const float* dec_Whh = (const float*)d_in[5];
    const float* dec_b   = (const float*)d_in[6];
    const float* pred_W  = (const float*)d_in[7];
    const float* pred_b  = (const float*)d_in[8];

    // Output layout hedge: default = concat(latents[65536], seq[6701056]).
    float* lat = (float*)d_out;
    float* seq = (float*)d_out + Bb*Hh;
    if (out_size == Bb*Hh)            { seq = 0; }
    else if (out_size == TB*Dd)       { lat = 0; seq = (float*)d_out; }

    float* gxe = symaddr(g_gx_enc);
    float* gxd = symaddr(g_gx_dec);
    float* hsb = symaddr(g_hs);
    float* h0  = symaddr(g_h0);
    float* h1  = symaddr(g_h1);

    k_zero2<<<(Bb*Hh + 255)/256, 256>>>(h0, symaddr(g_c), Bb*Hh);

    dim3 gg(G4/64, TB/128);
    k_gates<<<gg, 256>>>(inputs, enc_Wih, enc_b, gxe, 0);
    k_gates<<<gg, 256>>>(inputs, dec_Wih, dec_b, gxd, 1);

    float* hb[2] = {h0, h1};
    int cur = 0;
    for (int t = 0; t < Tt; t++){
        k_step<<<128, 256>>>(enc_Whh, gxe, hb[cur], hb[1-cur], (float*)0, t);
        cur ^= 1;
    }
    // cur == 0 again: final encoder h lives in h0
    if (lat) k_copy<<<(Bb*Hh + 255)/256, 256>>>(h0, lat, Bb*Hh);

    for (int t = 0; t < Tt; t++){
        k_step<<<128, 256>>>(dec_Whh, gxd, hb[cur], hb[1-cur], hsb, t);
        cur ^= 1;
    }

    if (seq){
        dim3 hg((Dd + 63)/64, TB/128);
        k_head<<<hg, 256>>>(pred_W, pred_b, seq);
    }
}

// round 7
// speedup vs baseline: 1.1708x; 1.1708x over previous
#include <cuda_runtime.h>
#include <stdint.h>
#include <math.h>

#define Bb 64
#define Tt 256
#define Dd 409
#define Hh 1024
#define G4 4096
#define TB 16384   // B*T
#define NCTA 128

typedef unsigned long long u64;

// All row indices are m = b*Tt + t (native [B,T,...] order)
__device__ float g_gx_enc[(size_t)TB*G4];   // x[m] @ Wih^T + b
__device__ float g_gx_dec[(size_t)TB*G4];   // x[m-1 or 0] @ Wih^T + b
__device__ float g_hs[(size_t)TB*Hh];       // decoder h, row m = b*Tt+t
__device__ float g_hA[Bb*Hh];
__device__ float g_hB[Bb*Hh];
__device__ unsigned g_cnt = 0;              // grid barrier arrival count
__device__ unsigned g_gen = 0;              // grid barrier generation

__device__ __forceinline__ void fma2(u64& d, u64 a, u64 b){
    asm("fma.rn.f32x2 %0, %1, %2, %0;" : "+l"(d) : "l"(a), "l"(b));
}
__device__ __forceinline__ float hsum(u64 v){
    float x, y;
    asm("mov.b64 {%0,%1}, %2;" : "=f"(x), "=f"(y) : "l"(v));
    return x + y;
}

__global__ void k_zero1(float* a, int n){
    int i = blockIdx.x*blockDim.x + threadIdx.x;
    if (i < n) a[i] = 0.f;
}

// ---- gates from x: gx[m][n] = x_row(m) . Wih[n] + bias[n]   (unchanged, passed R6)
__global__ void k_gates(const float* __restrict__ x, const float* __restrict__ W,
                        const float* __restrict__ bias, float* __restrict__ gx,
                        int shifted){
    __shared__ float Asf[8*260];
    __shared__ float Bsf[8*132];

    int tid = threadIdx.x, tm = tid >> 4, tn = tid & 15;
    int m0 = blockIdx.y * 128, n0 = blockIdx.x * 64;

    u64 acc[8][4];
    #pragma unroll
    for (int i=0;i<8;i++)
        #pragma unroll
        for (int j=0;j<4;j++) acc[i][j] = 0ull;

    for (int kt = 0; kt < 26; kt++){
        int k0 = kt * 16;
        #pragma unroll
        for (int q = 0; q < 8; q++){
            int idx = tid + q*256, ml = idx >> 4, kk = idx & 15;
            int k = k0 + kk, m = m0 + ml;
            float v = 0.f;
            if (k < Dd){
                if (!shifted)            v = x[(size_t)m*Dd + k];
                else if ((m & 255) != 0) v = x[(size_t)(m-1)*Dd + k];
            }
            Asf[(kk>>1)*260 + 2*ml + (kk&1)] = v;
        }
        #pragma unroll
        for (int q = 0; q < 4; q++){
            int idx = tid + q*256, nl = idx >> 4, kk = idx & 15;
            int k = k0 + kk;
            float v = (k < Dd) ? W[(size_t)(n0 + nl)*Dd + k] : 0.f;
            Bsf[(kk>>1)*132 + 2*nl + (kk&1)] = v;
        }
        __syncthreads();
        const u64* Au = (const u64*)Asf;
        const u64* Bu = (const u64*)Bsf;
        #pragma unroll
        for (int kp = 0; kp < 8; kp++){
            u64 a[8], b[4];
            #pragma unroll
            for (int i=0;i<8;i++) a[i] = Au[kp*130 + i*16 + tm];
            #pragma unroll
            for (int j=0;j<4;j++) b[j] = Bu[kp*66 + j*16 + tn];
            #pragma unroll
            for (int i=0;i<8;i++)
                #pragma unroll
                for (int j=0;j<4;j++) fma2(acc[i][j], a[i], b[j]);
        }
        __syncthreads();
    }
    #pragma unroll
    for (int j=0;j<4;j++){
        int n = n0 + j*16 + tn;
        float bv = bias[n];
        #pragma unroll
        for (int i=0;i<8;i++)
            gx[(size_t)(m0 + i*16 + tm)*G4 + n] = hsum(acc[i][j]) + bv;
    }
}

// ---- grid-wide generation barrier (all NCTA CTAs co-resident) ----
__device__ __forceinline__ void grid_bar(){
    __threadfence();
    __syncthreads();
    if (threadIdx.x == 0){
        volatile unsigned* vgen = &g_gen;
        unsigned gen = *vgen;
        unsigned t = atomicAdd(&g_cnt, 1u);
        if (t == NCTA - 1){
            g_cnt = 0;
            __threadfence();
            *vgen = gen + 1;
        } else {
            while (*vgen == gen) { }
        }
        __threadfence();
    }
    __syncthreads();
}

// ---- persistent recurrence: 512 steps (256 enc + 256 dec), Whh smem-resident,
// c-state in registers, grid barrier between steps. 128 CTAs x 256 thr.
__global__ void __launch_bounds__(256, 1) k_recur(
    const float* __restrict__ WhhE, const float* __restrict__ WhhD,
    float* __restrict__ lat)
{
    extern __shared__ float2 sm2[];
    float2* Ws2 = sm2;              // 32 rows x 513 (padded; conflict-free)
    float2* Hs2 = sm2 + 32*513;     // 32 kp   x 65

    int tid = threadIdx.x;
    int tm = tid >> 3, tn = tid & 7;     // tm: batch 0..31, tn: h-col 0..7
    int base = blockIdx.x * 8, gc = base + tn;

    const float2* WE2 = (const float2*)WhhE;
    const float2* WD2 = (const float2*)WhhD;

    // load encoder Whh slice (rows: gate g = r>>3, local col = r&7)
    for (int idx = tid; idx < 32*512; idx += 256){
        int r = idx >> 9, kk = idx & 511;
        int grow = ((r >> 3) << 10) + base + (r & 7);
        Ws2[r*513 + kk] = WE2[(size_t)grow*512 + kk];
    }

    float cst0 = 0.f, cst1 = 0.f;        // cell state, register-resident
    float* hA = g_hA;
    float* hB = g_hB;

    __syncthreads();

    for (int t = 0; t < 512; t++){
        int phase = t >> 8, tt = t & 255;
        if (t == 256){
            __syncthreads();
            for (int idx = tid; idx < 32*512; idx += 256){
                int r = idx >> 9, kk = idx & 511;
                int grow = ((r >> 3) << 10) + base + (r & 7);
                Ws2[r*513 + kk] = WD2[(size_t)grow*512 + kk];
            }
            __syncthreads();
        }
        const float2* Hin2 = (const float2*)((t & 1) ? hB : hA);
        float* hout = (t & 1) ? hA : hB;
        const float* gxP = phase ? g_gx_dec : g_gx_enc;

        // prefetch gx operands (DRAM latency hidden under GEMM)
        float gxv[2][4];
        #pragma unroll
        for (int i=0;i<2;i++){
            const float* gxr = gxP + ((size_t)(i*32+tm)*Tt + tt)*G4;
            #pragma unroll
            for (int j=0;j<4;j++) gxv[i][j] = gxr[j*Hh + gc];
        }

        u64 acc[2][4];
        #pragma unroll
        for (int i=0;i<2;i++)
            #pragma unroll
            for (int j=0;j<4;j++) acc[i][j] = 0ull;

        // prologue: prefetch h tile 0 into registers
        float2 pf[8];
        #pragma unroll
        for (int q=0;q<8;q++){
            int idx = tid + q*256, ml = idx >> 5, kp = idx & 31;
            pf[q] = Hin2[(size_t)ml*512 + kp];
        }

        for (int kt = 0; kt < 16; kt++){
            __syncthreads();                 // prev compute done; tile reusable
            #pragma unroll
            for (int q=0;q<8;q++){
                int idx = tid + q*256, ml = idx >> 5, kp = idx & 31;
                Hs2[kp*65 + ml] = pf[q];
            }
            __syncthreads();                 // tile ready
            if (kt < 15){
                int kb = (kt+1)*32;
                #pragma unroll
                for (int q=0;q<8;q++){
                    int idx = tid + q*256, ml = idx >> 5, kp = idx & 31;
                    pf[q] = Hin2[(size_t)ml*512 + kb + kp];
                }
            }
            int kb0 = kt*32;
            #pragma unroll
            for (int kp = 0; kp < 32; kp++){
                u64 a0 = *(const u64*)&Hs2[kp*65 + tm];
                u64 a1 = *(const u64*)&Hs2[kp*65 + 32 + tm];
                u64 b0 = *(const u64*)&Ws2[(     tn)*513 + kb0 + kp];
                u64 b1 = *(const u64*)&Ws2[( 8 + tn)*513 + kb0 + kp];
                u64 b2 = *(const u64*)&Ws2[(16 + tn)*513 + kb0 + kp];
                u64 b3 = *(const u64*)&Ws2[(24 + tn)*513 + kb0 + kp];
                fma2(acc[0][0], a0, b0); fma2(acc[0][1], a0, b1);
                fma2(acc[0][2], a0, b2); fma2(acc[0][3], a0, b3);
                fma2(acc[1][0], a1, b0); fma2(acc[1][1], a1, b1);
                fma2(acc[1][2], a1, b2); fma2(acc[1][3], a1, b3);
            }
        }

        // fused LSTM pointwise (gate quadruple + c entirely in registers)
        #pragma unroll
        for (int i=0;i<2;i++){
            int m = i*32 + tm;
            float iv = hsum(acc[i][0]) + gxv[i][0];
            float fv = hsum(acc[i][1]) + gxv[i][1];
            float gv = hsum(acc[i][2]) + gxv[i][2];
            float ov = hsum(acc[i][3]) + gxv[i][3];
            float si = 1.f / (1.f + expf(-iv));
            float sf = 1.f / (1.f + expf(-fv));
            float so = 1.f / (1.f + expf(-ov));
            float cc = i ? cst1 : cst0;
            cc = sf * cc + si * tanhf(gv);
            float h = so * tanhf(cc);
            if (i) cst1 = cc; else cst0 = cc;
            hout[m*Hh + gc] = h;
            if (phase)    g_hs[((size_t)m*Tt + tt)*Hh + gc] = h;
            if (t == 255) lat[m*Hh + gc] = h;
        }
        grid_bar();
    }
}

// ---- head: seq[m][n] = hs[m] . pred_W[n] + pred_b[n]   (unchanged, passed R6)
__global__ void k_head(const float* __restrict__ P, const float* __restrict__ pb,
                       float* __restrict__ seq){
    const float2* __restrict__ H2 = (const float2*)g_hs;
    const float2* __restrict__ P2 = (const float2*)P;

    __shared__ float2 As2[8*130];
    __shared__ float2 Bs2[8*66];

    int tid = threadIdx.x, tm = tid >> 4, tn = tid & 15;
    int m0 = blockIdx.y * 128, n0 = blockIdx.x * 64;

    u64 acc[8][4];
    #pragma unroll
    for (int i=0;i<8;i++)
        #pragma unroll
        for (int j=0;j<4;j++) acc[i][j] = 0ull;

    for (int kt = 0; kt < 64; kt++){
        int kb = kt * 8;
        #pragma unroll
        for (int q = 0; q < 4; q++){
            int idx = tid + q*256, ml = idx >> 3, kp = idx & 7;
            As2[kp*130 + ml] = H2[(size_t)(m0 + ml)*512 + kb + kp];
        }
        #pragma unroll
        for (int q = 0; q < 2; q++){
            int idx = tid + q*256, nl = idx >> 3, kp = idx & 7;
            int row = n0 + nl;
            float2 v = make_float2(0.f, 0.f);
            if (row < Dd) v = P2[(size_t)row*512 + kb + kp];
            Bs2[kp*66 + nl] = v;
        }
        __syncthreads();
        #pragma unroll
        for (int kp = 0; kp < 8; kp++){
            u64 a[8], b[4];
            #pragma unroll
            for (int i=0;i<8;i++) a[i] = *(const u64*)&As2[kp*130 + i*16 + tm];
            #pragma unroll
            for (int j=0;j<4;j++) b[j] = *(const u64*)&Bs2[kp*66 + j*16 + tn];
            #pragma unroll
            for (int i=0;i<8;i++)
                #pragma unroll
                for (int j=0;j<4;j++) fma2(acc[i][j], a[i], b[j]);
        }
        __syncthreads();
    }
    #pragma unroll
    for (int j=0;j<4;j++){
        int n = n0 + j*16 + tn;
        if (n >= Dd) continue;
        float bv = pb[n];
        #pragma unroll
        for (int i=0;i<8;i++)
            seq[(size_t)(m0 + i*16 + tm)*Dd + n] = hsum(acc[i][j]) + bv;
    }
}

static float* symaddr(const void* sym){
    void* p = 0;
    cudaGetSymbolAddress(&p, sym);
    return (float*)p;
}

extern "C" void kernel_launch(void* const* d_in, const int* in_sizes, int n_in,
                              void* d_out, int out_size) {
    const float* inputs  = (const float*)d_in[0];
    const float* enc_Wih = (const float*)d_in[1];
    const float* enc_Whh = (const float*)d_in[2];
    const float* enc_b   = (const float*)d_in[3];
    const float* dec_Wih = (const float*)d_in[4];
    const float* dec_Whh = (const float*)d_in[5];
    const float* dec_b   = (const float*)d_in[6];
    const float* pred_W  = (const float*)d_in[7];
    const float* pred_b  = (const float*)d_in[8];

    float* lat = (float*)d_out;               // [1,B,H]
    float* seq = (float*)d_out + Bb*Hh;       // [B,T,D]

    float* gxe = symaddr(g_gx_enc);
    float* gxd = symaddr(g_gx_dec);
    float* hA  = symaddr(g_hA);

    k_zero1<<<(Bb*Hh + 255)/256, 256>>>(hA, Bb*Hh);

    dim3 gg(G4/64, TB/128);
    k_gates<<<gg, 256>>>(inputs, enc_Wih, enc_b, gxe, 0);
    k_gates<<<gg, 256>>>(inputs, dec_Wih, dec_b, gxd, 1);

    // persistent recurrence: 148 SMs, 128 CTAs, 1 CTA/SM (smem-forced) => co-resident
    const int smem_bytes = (32*513 + 32*65) * (int)sizeof(float2);  // 147,968
    cudaFuncSetAttribute(k_recur, cudaFuncAttributeMaxDynamicSharedMemorySize, smem_bytes);
    k_recur<<<NCTA, 256, smem_bytes>>>(enc_Whh, dec_Whh, lat);

    dim3 hg((Dd + 63)/64, TB/128);
    k_head<<<hg, 256>>>(pred_W, pred_b, seq);
}